// round 1
// baseline (speedup 1.0000x reference)
#include <cuda_runtime.h>
#include <math.h>

#define B 4
#define S 2048
#define D 1024
#define M_TOT (B * S)   // 8192

// ---- scratch (device globals; no runtime allocation) ----
__device__ float g_q[(size_t)M_TOT * D];            // 32 MB
__device__ float g_k[(size_t)M_TOT * D];            // 32 MB
__device__ float g_v[(size_t)M_TOT * D];            // 32 MB
__device__ float g_s[(size_t)B * S * S];            // 64 MB (scores / probs)

#define BM 128
#define BN 128
#define BK 8
#define TM 8
#define TN 8
// 256 threads = 16x16 thread tile grid

// ============================================================
// Kernel 1: fused QKV projection.  Y = X @ W, X:[8192,1024], W:[1024,1024]
// blockIdx.z in {0,1,2} selects (Wq,g_q), (Wk,g_k), (Wv,g_v)
// ============================================================
__global__ __launch_bounds__(256) void qkv_gemm(
    const float* __restrict__ x,
    const float* __restrict__ Wq,
    const float* __restrict__ Wk,
    const float* __restrict__ Wv)
{
    const int which = blockIdx.z;
    const float* __restrict__ W = (which == 0) ? Wq : (which == 1) ? Wk : Wv;
    float* __restrict__ out = (which == 0) ? g_q : (which == 1) ? g_k : g_v;

    const int m0 = blockIdx.y * BM;
    const int n0 = blockIdx.x * BN;

    __shared__ float As[BK][BM];
    __shared__ float Bs[BK][BN];

    const int tid = threadIdx.x;
    const int arow = tid >> 1;          // 0..127
    const int acol = (tid & 1) * 4;     // 0 or 4
    const int brow = tid >> 5;          // 0..7
    const int bcol = (tid & 31) * 4;    // 0..124
    const int ty = tid >> 4;            // 0..15
    const int tx = tid & 15;            // 0..15

    float acc[TM][TN];
#pragma unroll
    for (int i = 0; i < TM; i++)
#pragma unroll
        for (int j = 0; j < TN; j++) acc[i][j] = 0.f;

    for (int k0 = 0; k0 < D; k0 += BK) {
        float4 a = *(const float4*)&x[(size_t)(m0 + arow) * D + k0 + acol];
        As[acol + 0][arow] = a.x;
        As[acol + 1][arow] = a.y;
        As[acol + 2][arow] = a.z;
        As[acol + 3][arow] = a.w;
        float4 b = *(const float4*)&W[(size_t)(k0 + brow) * D + n0 + bcol];
        *(float4*)&Bs[brow][bcol] = b;
        __syncthreads();
#pragma unroll
        for (int k = 0; k < BK; k++) {
            float ar[TM], br[TN];
#pragma unroll
            for (int i = 0; i < TM; i++) ar[i] = As[k][ty * TM + i];
#pragma unroll
            for (int j = 0; j < TN; j++) br[j] = Bs[k][tx * TN + j];
#pragma unroll
            for (int i = 0; i < TM; i++)
#pragma unroll
                for (int j = 0; j < TN; j++) acc[i][j] += ar[i] * br[j];
        }
        __syncthreads();
    }

#pragma unroll
    for (int i = 0; i < TM; i++) {
        const size_t row = (size_t)(m0 + ty * TM + i) * D + n0 + tx * TN;
#pragma unroll
        for (int j = 0; j < TN; j += 4) {
            float4 v4 = make_float4(acc[i][j], acc[i][j + 1], acc[i][j + 2], acc[i][j + 3]);
            *(float4*)&out[row + j] = v4;
        }
    }
}

// ============================================================
// Kernel 2: scores = (Q @ K^T) * scale, causal mask.
// NT GEMM: both operands [S, D] row-major, reduce along D.
// Fully-masked upper-triangular tiles are skipped (never read later).
// Diagonal tiles write -inf for k > q so softmax padding -> 0.
// ============================================================
__global__ __launch_bounds__(256) void scores_gemm()
{
    if (blockIdx.x > blockIdx.y) return;   // fully above diagonal -> skip

    const int b  = blockIdx.z;
    const int q0 = blockIdx.y * BM;
    const int k0t = blockIdx.x * BN;

    const float* __restrict__ Q  = g_q + (size_t)b * S * D;
    const float* __restrict__ Kp = g_k + (size_t)b * S * D;
    float* __restrict__ Sc = g_s + (size_t)b * S * S;

    __shared__ float As[BK][BM];
    __shared__ float Bs[BK][BN];

    const int tid = threadIdx.x;
    const int arow = tid >> 1;
    const int acol = (tid & 1) * 4;
    const int ty = tid >> 4;
    const int tx = tid & 15;

    float acc[TM][TN];
#pragma unroll
    for (int i = 0; i < TM; i++)
#pragma unroll
        for (int j = 0; j < TN; j++) acc[i][j] = 0.f;

    for (int d0 = 0; d0 < D; d0 += BK) {
        float4 a = *(const float4*)&Q[(size_t)(q0 + arow) * D + d0 + acol];
        As[acol + 0][arow] = a.x;
        As[acol + 1][arow] = a.y;
        As[acol + 2][arow] = a.z;
        As[acol + 3][arow] = a.w;
        float4 bb = *(const float4*)&Kp[(size_t)(k0t + arow) * D + d0 + acol];
        Bs[acol + 0][arow] = bb.x;
        Bs[acol + 1][arow] = bb.y;
        Bs[acol + 2][arow] = bb.z;
        Bs[acol + 3][arow] = bb.w;
        __syncthreads();
#pragma unroll
        for (int k = 0; k < BK; k++) {
            float ar[TM], br[TN];
#pragma unroll
            for (int i = 0; i < TM; i++) ar[i] = As[k][ty * TM + i];
#pragma unroll
            for (int j = 0; j < TN; j++) br[j] = Bs[k][tx * TN + j];
#pragma unroll
            for (int i = 0; i < TM; i++)
#pragma unroll
                for (int j = 0; j < TN; j++) acc[i][j] += ar[i] * br[j];
        }
        __syncthreads();
    }

    const float scale = 0.03125f;   // 1/sqrt(1024)
#pragma unroll
    for (int i = 0; i < TM; i++) {
        const int qi = q0 + ty * TM + i;
#pragma unroll
        for (int j = 0; j < TN; j++) {
            const int kj = k0t + tx * TN + j;
            float v = acc[i][j] * scale;
            if (kj > qi) v = -INFINITY;
            Sc[(size_t)qi * S + kj] = v;
        }
    }
}

// ============================================================
// Kernel 3: row softmax over the causal length padded to the
// 128-tile boundary (-inf entries -> 0, giving clean pad for PV).
// One block of 256 threads per row; 8192 rows.
// ============================================================
__global__ __launch_bounds__(256) void softmax_kernel()
{
    const int row = blockIdx.x;
    const int b = row >> 11;
    const int q = row & (S - 1);
    float* __restrict__ p = g_s + (size_t)b * S * S + (size_t)q * S;
    const int len = ((q >> 7) + 1) << 7;    // q-tile boundary

    __shared__ float red[256];
    const int t = threadIdx.x;

    float m = -INFINITY;
    for (int j = t; j < len; j += 256) m = fmaxf(m, p[j]);
    red[t] = m;
    __syncthreads();
    for (int s = 128; s > 0; s >>= 1) {
        if (t < s) red[t] = fmaxf(red[t], red[t + s]);
        __syncthreads();
    }
    m = red[0];
    __syncthreads();

    float sum = 0.f;
    for (int j = t; j < len; j += 256) {
        float e = expf(p[j] - m);   // expf(-inf)=0 handles mask + pad
        p[j] = e;
        sum += e;
    }
    red[t] = sum;
    __syncthreads();
    for (int s = 128; s > 0; s >>= 1) {
        if (t < s) red[t] += red[t + s];
        __syncthreads();
    }
    const float inv = 1.f / red[0];
    __syncthreads();

    for (int j = t; j < len; j += 256) p[j] *= inv;
}

// ============================================================
// Kernel 4: out = P @ V. NN GEMM, k-loop truncated at q-tile
// boundary (entries beyond it are exactly 0 anyway per kernel 3,
// but we never read past q0+BM -> causal flop saving).
// ============================================================
__global__ __launch_bounds__(256) void pv_gemm(float* __restrict__ outp)
{
    const int b  = blockIdx.z;
    const int q0 = blockIdx.y * BM;
    const int n0 = blockIdx.x * BN;

    const float* __restrict__ P = g_s + (size_t)b * S * S;
    const float* __restrict__ V = g_v + (size_t)b * S * D;
    float* __restrict__ out = outp + (size_t)b * S * D;

    __shared__ float As[BK][BM];
    __shared__ float Bs[BK][BN];

    const int tid = threadIdx.x;
    const int arow = tid >> 1;
    const int acol = (tid & 1) * 4;
    const int brow = tid >> 5;
    const int bcol = (tid & 31) * 4;
    const int ty = tid >> 4;
    const int tx = tid & 15;

    float acc[TM][TN];
#pragma unroll
    for (int i = 0; i < TM; i++)
#pragma unroll
        for (int j = 0; j < TN; j++) acc[i][j] = 0.f;

    const int kmax = q0 + BM;   // causal limit for this q tile
    for (int k0 = 0; k0 < kmax; k0 += BK) {
        float4 a = *(const float4*)&P[(size_t)(q0 + arow) * S + k0 + acol];
        As[acol + 0][arow] = a.x;
        As[acol + 1][arow] = a.y;
        As[acol + 2][arow] = a.z;
        As[acol + 3][arow] = a.w;
        float4 bb = *(const float4*)&V[(size_t)(k0 + brow) * D + n0 + bcol];
        *(float4*)&Bs[brow][bcol] = bb;
        __syncthreads();
#pragma unroll
        for (int k = 0; k < BK; k++) {
            float ar[TM], br[TN];
#pragma unroll
            for (int i = 0; i < TM; i++) ar[i] = As[k][ty * TM + i];
#pragma unroll
            for (int j = 0; j < TN; j++) br[j] = Bs[k][tx * TN + j];
#pragma unroll
            for (int i = 0; i < TM; i++)
#pragma unroll
                for (int j = 0; j < TN; j++) acc[i][j] += ar[i] * br[j];
        }
        __syncthreads();
    }

#pragma unroll
    for (int i = 0; i < TM; i++) {
        const size_t row = (size_t)(q0 + ty * TM + i) * D + n0 + tx * TN;
#pragma unroll
        for (int j = 0; j < TN; j += 4) {
            float4 v4 = make_float4(acc[i][j], acc[i][j + 1], acc[i][j + 2], acc[i][j + 3]);
            *(float4*)&out[row + j] = v4;
        }
    }
}

// ============================================================
extern "C" void kernel_launch(void* const* d_in, const int* in_sizes, int n_in,
                              void* d_out, int out_size)
{
    const float* x  = (const float*)d_in[0];
    const float* Wq = (const float*)d_in[1];
    const float* Wk = (const float*)d_in[2];
    const float* Wv = (const float*)d_in[3];
    float* out = (float*)d_out;

    dim3 g1(D / BN, M_TOT / BM, 3);      // (8, 64, 3)
    qkv_gemm<<<g1, 256>>>(x, Wq, Wk, Wv);

    dim3 g2(S / BN, S / BM, B);          // (16, 16, 4)
    scores_gemm<<<g2, 256>>>();

    softmax_kernel<<<M_TOT, 256>>>();

    dim3 g4(D / BN, S / BM, B);          // (8, 16, 4)
    pv_gemm<<<g4, 256>>>(out);
}

// round 3
// speedup vs baseline: 2.8901x; 2.8901x over previous
#include <cuda_runtime.h>
#include <cuda_bf16.h>
#include <math.h>
#include <stdint.h>

#define BATCH 4
#define SEQ   2048
#define DIM   1024
#define MTOT  (BATCH * SEQ)   // 8192

// ======================= device scratch (no runtime alloc) =======================
__device__ __align__(128) __nv_bfloat16 g_xhi[(size_t)MTOT * DIM];
__device__ __align__(128) __nv_bfloat16 g_xlo[(size_t)MTOT * DIM];
__device__ __align__(128) __nv_bfloat16 g_whi[3][(size_t)DIM * DIM];   // [din][dout]
__device__ __align__(128) __nv_bfloat16 g_wlo[3][(size_t)DIM * DIM];
__device__ __align__(128) __nv_bfloat16 g_qhi[(size_t)MTOT * DIM];
__device__ __align__(128) __nv_bfloat16 g_qlo[(size_t)MTOT * DIM];
__device__ __align__(128) __nv_bfloat16 g_khi[(size_t)MTOT * DIM];
__device__ __align__(128) __nv_bfloat16 g_klo[(size_t)MTOT * DIM];
__device__ __align__(128) __nv_bfloat16 g_vhi[(size_t)MTOT * DIM];
__device__ __align__(128) __nv_bfloat16 g_vlo[(size_t)MTOT * DIM];
__device__ __align__(128) float         g_s[(size_t)BATCH * SEQ * SEQ];
__device__ __align__(128) __nv_bfloat16 g_phi[(size_t)BATCH * SEQ * SEQ];
__device__ __align__(128) __nv_bfloat16 g_plo[(size_t)BATCH * SEQ * SEQ];

// ======================= PTX helpers (arch-agnostic, sm_80-era) =======================
__device__ __forceinline__ uint32_t smem_u32(const void* p) {
    uint32_t a;
    asm("{ .reg .u64 t; cvta.to.shared.u64 t, %1; cvt.u32.u64 %0, t; }" : "=r"(a) : "l"(p));
    return a;
}
__device__ __forceinline__ void cp16(uint32_t dst, const void* src) {
    asm volatile("cp.async.cg.shared.global [%0], [%1], 16;" :: "r"(dst), "l"(src));
}
__device__ __forceinline__ void cp_commit() { asm volatile("cp.async.commit_group;"); }
template<int N>
__device__ __forceinline__ void cp_wait() { asm volatile("cp.async.wait_group %0;" :: "n"(N)); }

__device__ __forceinline__ void ldsm4(uint32_t* r, uint32_t a) {
    asm volatile("ldmatrix.sync.aligned.m8n8.x4.shared.b16 {%0,%1,%2,%3}, [%4];"
                 : "=r"(r[0]), "=r"(r[1]), "=r"(r[2]), "=r"(r[3]) : "r"(a));
}
__device__ __forceinline__ void ldsm4t(uint32_t* r, uint32_t a) {
    asm volatile("ldmatrix.sync.aligned.m8n8.x4.trans.shared.b16 {%0,%1,%2,%3}, [%4];"
                 : "=r"(r[0]), "=r"(r[1]), "=r"(r[2]), "=r"(r[3]) : "r"(a));
}
__device__ __forceinline__ void mma16816(float* c, const uint32_t* a, const uint32_t* b) {
    asm volatile(
        "mma.sync.aligned.m16n8k16.row.col.f32.bf16.bf16.f32 "
        "{%0,%1,%2,%3},{%4,%5,%6,%7},{%8,%9},{%0,%1,%2,%3};"
        : "+f"(c[0]), "+f"(c[1]), "+f"(c[2]), "+f"(c[3])
        : "r"(a[0]), "r"(a[1]), "r"(a[2]), "r"(a[3]), "r"(b[0]), "r"(b[1]));
}

// ======================= smem layout =======================
// A tile: 128 rows x 32 bf16, padded row stride 40 halves (80 B) -> 10240 B
// B tile (NK, [n][k]): same as A -> 10240 B
// B tile (KN, [k][n]): 32 rows x 128 bf16, padded stride 136 halves (272 B) -> 8704 B
// Layout: [Ahi0, Alo0, Ahi1, Alo1][Bhi0, Blo0, Bhi1, Blo1]
#define A_TILE_B   10240
#define SMEM_B_OFF 40960
#define SMEM_BYTES 81920

__device__ __forceinline__ void st_split2(__nv_bfloat16* hi, __nv_bfloat16* lo,
                                          size_t off, float f0, float f1) {
    __nv_bfloat16 h0 = __float2bfloat16(f0), h1 = __float2bfloat16(f1);
    __nv_bfloat16 l0 = __float2bfloat16(f0 - __bfloat162float(h0));
    __nv_bfloat16 l1 = __float2bfloat16(f1 - __bfloat162float(h1));
    uint32_t hp = (uint32_t)__bfloat16_as_ushort(h0) | ((uint32_t)__bfloat16_as_ushort(h1) << 16);
    uint32_t lp = (uint32_t)__bfloat16_as_ushort(l0) | ((uint32_t)__bfloat16_as_ushort(l1) << 16);
    *reinterpret_cast<uint32_t*>(hi + off) = hp;
    *reinterpret_cast<uint32_t*>(lo + off) = lp;
}

// ======================= generic split-bf16 tensor-core GEMM =======================
// C[128x128] = sum_k A[128xK] * B, A row-major (lda), split hi/lo.
// BKN=true : B stored [k][n] row-major (ldb = n-stride), uses ldmatrix.trans
// BKN=false: B stored [n][k] row-major (ldb = k-stride), uses ldmatrix
template<bool BKN>
__device__ __forceinline__ void gemm_run(
    const __nv_bfloat16* __restrict__ ahi, const __nv_bfloat16* __restrict__ alo, int lda,
    const __nv_bfloat16* __restrict__ bhi, const __nv_bfloat16* __restrict__ blo, int ldb,
    int nchunks, float (&acc)[4][4][4])
{
    extern __shared__ char smem[];
    const uint32_t sb = smem_u32(smem);
    const int tid = threadIdx.x;
    const int lane = tid & 31, warp = tid >> 5;
    const int wm = warp >> 2, wn = warp & 3;        // 2 x 4 warp grid, warp tile 64x32
    const int BT = BKN ? 8704 : 10240;

#pragma unroll
    for (int mi = 0; mi < 4; mi++)
#pragma unroll
        for (int ni = 0; ni < 4; ni++)
#pragma unroll
            for (int k = 0; k < 4; k++) acc[mi][ni][k] = 0.f;

    auto load_chunk = [&](int buf, int c) {
        const uint32_t ah = sb + (buf * 2 + 0) * A_TILE_B;
        const uint32_t al = sb + (buf * 2 + 1) * A_TILE_B;
        const uint32_t bh = sb + SMEM_B_OFF + (buf * 2 + 0) * BT;
        const uint32_t bl = sb + SMEM_B_OFF + (buf * 2 + 1) * BT;
        int i = tid;
#pragma unroll
        for (int j = 0; j < 2; j++, i += 256) {
            {   // A: 128 rows x 32 halves
                int row = i >> 2, cc = i & 3;
                size_t go = (size_t)row * lda + c * 32 + cc * 8;
                uint32_t so = (uint32_t)row * 80u + (uint32_t)cc * 16u;
                cp16(ah + so, ahi + go);
                cp16(al + so, alo + go);
            }
            if (BKN) {  // B: 32 k-rows x 128 halves
                int row = i >> 4, cc = i & 15;
                size_t go = (size_t)(c * 32 + row) * ldb + cc * 8;
                uint32_t so = (uint32_t)row * 272u + (uint32_t)cc * 16u;
                cp16(bh + so, bhi + go);
                cp16(bl + so, blo + go);
            } else {    // B: 128 n-rows x 32 halves
                int row = i >> 2, cc = i & 3;
                size_t go = (size_t)row * ldb + c * 32 + cc * 8;
                uint32_t so = (uint32_t)row * 80u + (uint32_t)cc * 16u;
                cp16(bh + so, bhi + go);
                cp16(bl + so, blo + go);
            }
        }
        cp_commit();
    };

    load_chunk(0, 0);
    for (int c = 0; c < nchunks; ++c) {
        const int buf = c & 1;
        if (c + 1 < nchunks) { load_chunk(1 - buf, c + 1); cp_wait<1>(); }
        else                 { cp_wait<0>(); }
        __syncthreads();

        const uint32_t ah = sb + (buf * 2 + 0) * A_TILE_B;
        const uint32_t al = sb + (buf * 2 + 1) * A_TILE_B;
        const uint32_t bh = sb + SMEM_B_OFF + (buf * 2 + 0) * BT;
        const uint32_t bl = sb + SMEM_B_OFF + (buf * 2 + 1) * BT;

#pragma unroll
        for (int ks = 0; ks < 2; ++ks) {
            uint32_t Ah[4][4], Al[4][4], Bh[4][2], Bl[4][2];
            // A frags: ldmatrix.x4 per m16 tile (rows wm*64+mi*16+(lane&15), col ks*16+(lane>>4)*8)
            const uint32_t ao = (uint32_t)(wm * 64 + (lane & 15)) * 80u
                              + (uint32_t)(ks * 16 + (lane >> 4) * 8) * 2u;
#pragma unroll
            for (int mi = 0; mi < 4; mi++) {
                ldsm4(Ah[mi], ah + ao + (uint32_t)(mi * 16) * 80u);
                ldsm4(Al[mi], al + ao + (uint32_t)(mi * 16) * 80u);
            }
            if (BKN) {
                const uint32_t brow = (uint32_t)(ks * 16 + (lane & 15));
#pragma unroll
                for (int p = 0; p < 2; p++) {
                    const uint32_t bo = brow * 272u
                        + (uint32_t)(wn * 32 + p * 16 + (lane >> 4) * 8) * 2u;
                    uint32_t r[4];
                    ldsm4t(r, bh + bo);
                    Bh[2*p][0] = r[0]; Bh[2*p][1] = r[1];
                    Bh[2*p+1][0] = r[2]; Bh[2*p+1][1] = r[3];
                    ldsm4t(r, bl + bo);
                    Bl[2*p][0] = r[0]; Bl[2*p][1] = r[1];
                    Bl[2*p+1][0] = r[2]; Bl[2*p+1][1] = r[3];
                }
            } else {
                const uint32_t bcol2 = (uint32_t)(ks * 16 + ((lane >> 3) & 1) * 8) * 2u;
#pragma unroll
                for (int p = 0; p < 2; p++) {
                    const uint32_t brow = (uint32_t)(wn * 32 + p * 16 + (lane & 7) + ((lane >> 4) << 3));
                    const uint32_t bo = brow * 80u + bcol2;
                    uint32_t r[4];
                    ldsm4(r, bh + bo);
                    Bh[2*p][0] = r[0]; Bh[2*p][1] = r[1];
                    Bh[2*p+1][0] = r[2]; Bh[2*p+1][1] = r[3];
                    ldsm4(r, bl + bo);
                    Bl[2*p][0] = r[0]; Bl[2*p][1] = r[1];
                    Bl[2*p+1][0] = r[2]; Bl[2*p+1][1] = r[3];
                }
            }
#pragma unroll
            for (int mi = 0; mi < 4; mi++)
#pragma unroll
                for (int ni = 0; ni < 4; ni++) {
                    mma16816(acc[mi][ni], Ah[mi], Bh[ni]);
                    mma16816(acc[mi][ni], Ah[mi], Bl[ni]);
                    mma16816(acc[mi][ni], Al[mi], Bh[ni]);
                }
        }
        __syncthreads();
    }
}

// ======================= kernel: split fp32 -> bf16 hi/lo =======================
// which: 0=x, 1=Wq, 2=Wk, 3=Wv
__global__ __launch_bounds__(256) void split_kernel(const float* __restrict__ src, int which) {
    __nv_bfloat16 *hi, *lo;
    if (which == 0)      { hi = g_xhi;    lo = g_xlo;    }
    else if (which == 1) { hi = g_whi[0]; lo = g_wlo[0]; }
    else if (which == 2) { hi = g_whi[1]; lo = g_wlo[1]; }
    else                 { hi = g_whi[2]; lo = g_wlo[2]; }
    size_t base = ((size_t)blockIdx.x * 256 + threadIdx.x) * 4;
    float4 v = *reinterpret_cast<const float4*>(src + base);
    float f[4] = {v.x, v.y, v.z, v.w};
    uint32_t hp[2], lp[2];
#pragma unroll
    for (int j = 0; j < 2; j++) {
        __nv_bfloat16 h0 = __float2bfloat16(f[2*j]),   h1 = __float2bfloat16(f[2*j+1]);
        __nv_bfloat16 l0 = __float2bfloat16(f[2*j]   - __bfloat162float(h0));
        __nv_bfloat16 l1 = __float2bfloat16(f[2*j+1] - __bfloat162float(h1));
        hp[j] = (uint32_t)__bfloat16_as_ushort(h0) | ((uint32_t)__bfloat16_as_ushort(h1) << 16);
        lp[j] = (uint32_t)__bfloat16_as_ushort(l0) | ((uint32_t)__bfloat16_as_ushort(l1) << 16);
    }
    *reinterpret_cast<uint2*>(hi + base) = make_uint2(hp[0], hp[1]);
    *reinterpret_cast<uint2*>(lo + base) = make_uint2(lp[0], lp[1]);
}

// ======================= kernel: QKV projection =======================
__global__ __launch_bounds__(256) void qkv_gemm() {
    const int z = blockIdx.z, m0 = blockIdx.y * 128, n0 = blockIdx.x * 128;
    float acc[4][4][4];
    gemm_run<true>(g_xhi + (size_t)m0 * DIM, g_xlo + (size_t)m0 * DIM, DIM,
                   g_whi[z] + n0, g_wlo[z] + n0, DIM, DIM / 32, acc);
    __nv_bfloat16* oh = (z == 0) ? g_qhi : (z == 1) ? g_khi : g_vhi;
    __nv_bfloat16* ol = (z == 0) ? g_qlo : (z == 1) ? g_klo : g_vlo;
    const int lane = threadIdx.x & 31, warp = threadIdx.x >> 5;
    const int g = lane >> 2, t = lane & 3, wm = warp >> 2, wn = warp & 3;
#pragma unroll
    for (int mi = 0; mi < 4; mi++) {
        const int r0 = m0 + wm * 64 + mi * 16 + g;
#pragma unroll
        for (int ni = 0; ni < 4; ni++) {
            const int cc = n0 + wn * 32 + ni * 8 + 2 * t;
            st_split2(oh, ol, (size_t)r0 * DIM + cc,       acc[mi][ni][0], acc[mi][ni][1]);
            st_split2(oh, ol, (size_t)(r0 + 8) * DIM + cc, acc[mi][ni][2], acc[mi][ni][3]);
        }
    }
}

// ======================= kernel: scores = QK^T * scale (causal) =======================
__global__ __launch_bounds__(256) void scores_gemm() {
    if (blockIdx.x > blockIdx.y) return;     // fully-masked tile, never read later
    const int b = blockIdx.z, q0 = blockIdx.y * 128, k0 = blockIdx.x * 128;
    const size_t boff = (size_t)b * SEQ * DIM;
    float acc[4][4][4];
    gemm_run<false>(g_qhi + boff + (size_t)q0 * DIM, g_qlo + boff + (size_t)q0 * DIM, DIM,
                    g_khi + boff + (size_t)k0 * DIM, g_klo + boff + (size_t)k0 * DIM, DIM,
                    DIM / 32, acc);
    const bool diag = (blockIdx.x == blockIdx.y);
    float* sc = g_s + (size_t)b * SEQ * SEQ;
    const int lane = threadIdx.x & 31, warp = threadIdx.x >> 5;
    const int g = lane >> 2, t = lane & 3, wm = warp >> 2, wn = warp & 3;
    const float scale = 0.03125f;
#pragma unroll
    for (int mi = 0; mi < 4; mi++) {
        const int r0 = q0 + wm * 64 + mi * 16 + g;
#pragma unroll
        for (int ni = 0; ni < 4; ni++) {
            const int cc = k0 + wn * 32 + ni * 8 + 2 * t;
            float f0 = acc[mi][ni][0] * scale, f1 = acc[mi][ni][1] * scale;
            float f2 = acc[mi][ni][2] * scale, f3 = acc[mi][ni][3] * scale;
            if (diag) {
                if (cc     > r0)     f0 = -INFINITY;
                if (cc + 1 > r0)     f1 = -INFINITY;
                if (cc     > r0 + 8) f2 = -INFINITY;
                if (cc + 1 > r0 + 8) f3 = -INFINITY;
            }
            *reinterpret_cast<float2*>(sc + (size_t)r0 * SEQ + cc)       = make_float2(f0, f1);
            *reinterpret_cast<float2*>(sc + (size_t)(r0 + 8) * SEQ + cc) = make_float2(f2, f3);
        }
    }
}

// ======================= kernel: softmax -> split-bf16 probs =======================
__global__ __launch_bounds__(256) void softmax_kernel() {
    const int row = blockIdx.x;
    const int b = row >> 11;
    const int q = row & (SEQ - 1);
    float* __restrict__ p = g_s + (size_t)b * SEQ * SEQ + (size_t)q * SEQ;
    __nv_bfloat16* __restrict__ ph = g_phi + (size_t)b * SEQ * SEQ + (size_t)q * SEQ;
    __nv_bfloat16* __restrict__ pl = g_plo + (size_t)b * SEQ * SEQ + (size_t)q * SEQ;
    const int len = ((q >> 7) + 1) << 7;   // padded to 128-tile boundary

    __shared__ float red[256];
    const int t = threadIdx.x;

    float m = -INFINITY;
    for (int j = t; j < len; j += 256) m = fmaxf(m, p[j]);
    red[t] = m;
    __syncthreads();
    for (int s = 128; s > 0; s >>= 1) {
        if (t < s) red[t] = fmaxf(red[t], red[t + s]);
        __syncthreads();
    }
    m = red[0];
    __syncthreads();

    float sum = 0.f;
    for (int j = t; j < len; j += 256) {
        float e = expf(p[j] - m);      // expf(-inf)=0 handles mask + pad
        p[j] = e;
        sum += e;
    }
    red[t] = sum;
    __syncthreads();
    for (int s = 128; s > 0; s >>= 1) {
        if (t < s) red[t] += red[t + s];
        __syncthreads();
    }
    const float inv = 1.f / red[0];
    __syncthreads();

    for (int j = t; j < len; j += 256) {
        float pr = p[j] * inv;
        __nv_bfloat16 h = __float2bfloat16(pr);
        ph[j] = h;
        pl[j] = __float2bfloat16(pr - __bfloat162float(h));
    }
}

// ======================= kernel: O = P @ V (causal-truncated K) =======================
__global__ __launch_bounds__(256) void pv_gemm(float* __restrict__ outp) {
    const int b = blockIdx.z, q0 = blockIdx.y * 128, n0 = blockIdx.x * 128;
    float acc[4][4][4];
    gemm_run<true>(g_phi + (size_t)b * SEQ * SEQ + (size_t)q0 * SEQ,
                   g_plo + (size_t)b * SEQ * SEQ + (size_t)q0 * SEQ, SEQ,
                   g_vhi + (size_t)b * SEQ * DIM + n0,
                   g_vlo + (size_t)b * SEQ * DIM + n0, DIM,
                   (q0 + 128) / 32, acc);
    float* out = outp + (size_t)b * SEQ * DIM;
    const int lane = threadIdx.x & 31, warp = threadIdx.x >> 5;
    const int g = lane >> 2, t = lane & 3, wm = warp >> 2, wn = warp & 3;
#pragma unroll
    for (int mi = 0; mi < 4; mi++) {
        const int r0 = q0 + wm * 64 + mi * 16 + g;
#pragma unroll
        for (int ni = 0; ni < 4; ni++) {
            const int cc = n0 + wn * 32 + ni * 8 + 2 * t;
            *reinterpret_cast<float2*>(out + (size_t)r0 * DIM + cc) =
                make_float2(acc[mi][ni][0], acc[mi][ni][1]);
            *reinterpret_cast<float2*>(out + (size_t)(r0 + 8) * DIM + cc) =
                make_float2(acc[mi][ni][2], acc[mi][ni][3]);
        }
    }
}

// ======================= launch =======================
extern "C" void kernel_launch(void* const* d_in, const int* in_sizes, int n_in,
                              void* d_out, int out_size) {
    const float* x  = (const float*)d_in[0];
    const float* Wq = (const float*)d_in[1];
    const float* Wk = (const float*)d_in[2];
    const float* Wv = (const float*)d_in[3];
    float* out = (float*)d_out;

    cudaFuncSetAttribute(qkv_gemm,    cudaFuncAttributeMaxDynamicSharedMemorySize, SMEM_BYTES);
    cudaFuncSetAttribute(scores_gemm, cudaFuncAttributeMaxDynamicSharedMemorySize, SMEM_BYTES);
    cudaFuncSetAttribute(pv_gemm,     cudaFuncAttributeMaxDynamicSharedMemorySize, SMEM_BYTES);

    split_kernel<<<(size_t)MTOT * DIM / 1024, 256>>>(x, 0);
    split_kernel<<<(size_t)DIM * DIM / 1024, 256>>>(Wq, 1);
    split_kernel<<<(size_t)DIM * DIM / 1024, 256>>>(Wk, 2);
    split_kernel<<<(size_t)DIM * DIM / 1024, 256>>>(Wv, 3);

    qkv_gemm<<<dim3(DIM / 128, MTOT / 128, 3), 256, SMEM_BYTES>>>();
    scores_gemm<<<dim3(SEQ / 128, SEQ / 128, BATCH), 256, SMEM_BYTES>>>();
    softmax_kernel<<<MTOT, 256>>>();
    pv_gemm<<<dim3(DIM / 128, SEQ / 128, BATCH), 256, SMEM_BYTES>>>(out);
}

// round 4
// speedup vs baseline: 3.0897x; 1.0691x over previous
#include <cuda_runtime.h>
#include <cuda_bf16.h>
#include <cuda_fp16.h>
#include <math.h>
#include <stdint.h>

#define BATCH 4
#define SEQ   2048
#define DIM   1024
#define MTOT  (BATCH * SEQ)   // 8192

// ======================= device scratch (no runtime alloc) =======================
__device__ __align__(128) __nv_bfloat16 g_xhi[(size_t)MTOT * DIM];
__device__ __align__(128) __nv_bfloat16 g_xlo[(size_t)MTOT * DIM];
__device__ __align__(128) __nv_bfloat16 g_whi[3][(size_t)DIM * DIM];   // [din][dout]
__device__ __align__(128) __nv_bfloat16 g_wlo[3][(size_t)DIM * DIM];
__device__ __align__(128) __nv_bfloat16 g_qhi[(size_t)MTOT * DIM];
__device__ __align__(128) __nv_bfloat16 g_qlo[(size_t)MTOT * DIM];
__device__ __align__(128) __nv_bfloat16 g_khi[(size_t)MTOT * DIM];
__device__ __align__(128) __nv_bfloat16 g_klo[(size_t)MTOT * DIM];
__device__ __align__(128) __half        g_vh[(size_t)MTOT * DIM];         // fp16 V (hi only)
__device__ __align__(128) __half        g_phi[(size_t)BATCH * SEQ * SEQ]; // unnorm probs hi
__device__ __align__(128) __half        g_plo[(size_t)BATCH * SEQ * SEQ]; // unnorm probs lo
__device__ __align__(128) float         g_partial[BATCH][SEQ / 128][SEQ]; // rowsum partials
__device__ __align__(128) float         g_rsuminv[MTOT];                  // 1 / rowsum

// ======================= PTX helpers (arch-agnostic, sm_80-era) =======================
__device__ __forceinline__ uint32_t smem_u32(const void* p) {
    uint32_t a;
    asm("{ .reg .u64 t; cvta.to.shared.u64 t, %1; cvt.u32.u64 %0, t; }" : "=r"(a) : "l"(p));
    return a;
}
__device__ __forceinline__ void cp16(uint32_t dst, const void* src) {
    asm volatile("cp.async.cg.shared.global [%0], [%1], 16;" :: "r"(dst), "l"(src));
}
__device__ __forceinline__ void cp_commit() { asm volatile("cp.async.commit_group;"); }
template<int N>
__device__ __forceinline__ void cp_wait() { asm volatile("cp.async.wait_group %0;" :: "n"(N)); }

__device__ __forceinline__ void ldsm4(uint32_t* r, uint32_t a) {
    asm volatile("ldmatrix.sync.aligned.m8n8.x4.shared.b16 {%0,%1,%2,%3}, [%4];"
                 : "=r"(r[0]), "=r"(r[1]), "=r"(r[2]), "=r"(r[3]) : "r"(a));
}
__device__ __forceinline__ void ldsm4t(uint32_t* r, uint32_t a) {
    asm volatile("ldmatrix.sync.aligned.m8n8.x4.trans.shared.b16 {%0,%1,%2,%3}, [%4];"
                 : "=r"(r[0]), "=r"(r[1]), "=r"(r[2]), "=r"(r[3]) : "r"(a));
}
__device__ __forceinline__ void mma_bf16(float* c, const uint32_t* a, const uint32_t* b) {
    asm volatile(
        "mma.sync.aligned.m16n8k16.row.col.f32.bf16.bf16.f32 "
        "{%0,%1,%2,%3},{%4,%5,%6,%7},{%8,%9},{%0,%1,%2,%3};"
        : "+f"(c[0]), "+f"(c[1]), "+f"(c[2]), "+f"(c[3])
        : "r"(a[0]), "r"(a[1]), "r"(a[2]), "r"(a[3]), "r"(b[0]), "r"(b[1]));
}
__device__ __forceinline__ void mma_f16(float* c, const uint32_t* a, const uint32_t* b) {
    asm volatile(
        "mma.sync.aligned.m16n8k16.row.col.f32.f16.f16.f32 "
        "{%0,%1,%2,%3},{%4,%5,%6,%7},{%8,%9},{%0,%1,%2,%3};"
        : "+f"(c[0]), "+f"(c[1]), "+f"(c[2]), "+f"(c[3])
        : "r"(a[0]), "r"(a[1]), "r"(a[2]), "r"(a[3]), "r"(b[0]), "r"(b[1]));
}

// ======================= smem layout =======================
// A tile: 128 rows x 32 halves, padded row stride 40 halves (80 B) -> 10240 B
// B tile (NK, [n][k]): same as A -> 10240 B
// B tile (KN, [k][n]): 32 rows x 128 halves, padded stride 136 halves (272 B) -> 8704 B
#define A_TILE_B   10240
#define SMEM_B_OFF 40960
#define SMEM_BYTES 81920

__device__ __forceinline__ void st_split2_bf16(__nv_bfloat16* hi, __nv_bfloat16* lo,
                                               size_t off, float f0, float f1) {
    __nv_bfloat16 h0 = __float2bfloat16(f0), h1 = __float2bfloat16(f1);
    __nv_bfloat16 l0 = __float2bfloat16(f0 - __bfloat162float(h0));
    __nv_bfloat16 l1 = __float2bfloat16(f1 - __bfloat162float(h1));
    uint32_t hp = (uint32_t)__bfloat16_as_ushort(h0) | ((uint32_t)__bfloat16_as_ushort(h1) << 16);
    uint32_t lp = (uint32_t)__bfloat16_as_ushort(l0) | ((uint32_t)__bfloat16_as_ushort(l1) << 16);
    *reinterpret_cast<uint32_t*>(hi + off) = hp;
    *reinterpret_cast<uint32_t*>(lo + off) = lp;
}
__device__ __forceinline__ void st_split2_f16(__half* hi, __half* lo,
                                              size_t off, float f0, float f1) {
    __half h0 = __float2half_rn(f0), h1 = __float2half_rn(f1);
    __half l0 = __float2half_rn(f0 - __half2float(h0));
    __half l1 = __float2half_rn(f1 - __half2float(h1));
    uint32_t hp = (uint32_t)__half_as_ushort(h0) | ((uint32_t)__half_as_ushort(h1) << 16);
    uint32_t lp = (uint32_t)__half_as_ushort(l0) | ((uint32_t)__half_as_ushort(l1) << 16);
    *reinterpret_cast<uint32_t*>(hi + off) = hp;
    *reinterpret_cast<uint32_t*>(lo + off) = lp;
}

// ======================= 3-term split-bf16 tensor-core GEMM (128x128 tile) =======================
// BKN=true : B stored [k][n] row-major (ldb = n-stride), uses ldmatrix.trans
// BKN=false: B stored [n][k] row-major (ldb = k-stride), uses ldmatrix
template<bool BKN>
__device__ __forceinline__ void gemm3_bf16(
    const __nv_bfloat16* __restrict__ ahi, const __nv_bfloat16* __restrict__ alo, int lda,
    const __nv_bfloat16* __restrict__ bhi, const __nv_bfloat16* __restrict__ blo, int ldb,
    int nchunks, float (&acc)[4][4][4])
{
    extern __shared__ char smem[];
    const uint32_t sb = smem_u32(smem);
    const int tid = threadIdx.x;
    const int lane = tid & 31, warp = tid >> 5;
    const int wm = warp >> 2, wn = warp & 3;
    const int BT = BKN ? 8704 : 10240;

#pragma unroll
    for (int mi = 0; mi < 4; mi++)
#pragma unroll
        for (int ni = 0; ni < 4; ni++)
#pragma unroll
            for (int k = 0; k < 4; k++) acc[mi][ni][k] = 0.f;

    auto load_chunk = [&](int buf, int c) {
        const uint32_t ah = sb + (buf * 2 + 0) * A_TILE_B;
        const uint32_t al = sb + (buf * 2 + 1) * A_TILE_B;
        const uint32_t bh = sb + SMEM_B_OFF + (buf * 2 + 0) * BT;
        const uint32_t bl = sb + SMEM_B_OFF + (buf * 2 + 1) * BT;
        int i = tid;
#pragma unroll
        for (int j = 0; j < 2; j++, i += 256) {
            {
                int row = i >> 2, cc = i & 3;
                size_t go = (size_t)row * lda + c * 32 + cc * 8;
                uint32_t so = (uint32_t)row * 80u + (uint32_t)cc * 16u;
                cp16(ah + so, ahi + go);
                cp16(al + so, alo + go);
            }
            if (BKN) {
                int row = i >> 4, cc = i & 15;
                size_t go = (size_t)(c * 32 + row) * ldb + cc * 8;
                uint32_t so = (uint32_t)row * 272u + (uint32_t)cc * 16u;
                cp16(bh + so, bhi + go);
                cp16(bl + so, blo + go);
            } else {
                int row = i >> 2, cc = i & 3;
                size_t go = (size_t)row * ldb + c * 32 + cc * 8;
                uint32_t so = (uint32_t)row * 80u + (uint32_t)cc * 16u;
                cp16(bh + so, bhi + go);
                cp16(bl + so, blo + go);
            }
        }
        cp_commit();
    };

    load_chunk(0, 0);
    for (int c = 0; c < nchunks; ++c) {
        const int buf = c & 1;
        if (c + 1 < nchunks) { load_chunk(1 - buf, c + 1); cp_wait<1>(); }
        else                 { cp_wait<0>(); }
        __syncthreads();

        const uint32_t ah = sb + (buf * 2 + 0) * A_TILE_B;
        const uint32_t al = sb + (buf * 2 + 1) * A_TILE_B;
        const uint32_t bh = sb + SMEM_B_OFF + (buf * 2 + 0) * BT;
        const uint32_t bl = sb + SMEM_B_OFF + (buf * 2 + 1) * BT;

#pragma unroll
        for (int ks = 0; ks < 2; ++ks) {
            uint32_t Ah[4][4], Al[4][4], Bh[4][2], Bl[4][2];
            const uint32_t ao = (uint32_t)(wm * 64 + (lane & 15)) * 80u
                              + (uint32_t)(ks * 16 + (lane >> 4) * 8) * 2u;
#pragma unroll
            for (int mi = 0; mi < 4; mi++) {
                ldsm4(Ah[mi], ah + ao + (uint32_t)(mi * 16) * 80u);
                ldsm4(Al[mi], al + ao + (uint32_t)(mi * 16) * 80u);
            }
            if (BKN) {
                const uint32_t brow = (uint32_t)(ks * 16 + (lane & 15));
#pragma unroll
                for (int p = 0; p < 2; p++) {
                    const uint32_t bo = brow * 272u
                        + (uint32_t)(wn * 32 + p * 16 + (lane >> 4) * 8) * 2u;
                    uint32_t r[4];
                    ldsm4t(r, bh + bo);
                    Bh[2*p][0] = r[0]; Bh[2*p][1] = r[1];
                    Bh[2*p+1][0] = r[2]; Bh[2*p+1][1] = r[3];
                    ldsm4t(r, bl + bo);
                    Bl[2*p][0] = r[0]; Bl[2*p][1] = r[1];
                    Bl[2*p+1][0] = r[2]; Bl[2*p+1][1] = r[3];
                }
            } else {
                const uint32_t bcol2 = (uint32_t)(ks * 16 + ((lane >> 3) & 1) * 8) * 2u;
#pragma unroll
                for (int p = 0; p < 2; p++) {
                    const uint32_t brow = (uint32_t)(wn * 32 + p * 16 + (lane & 7) + ((lane >> 4) << 3));
                    const uint32_t bo = brow * 80u + bcol2;
                    uint32_t r[4];
                    ldsm4(r, bh + bo);
                    Bh[2*p][0] = r[0]; Bh[2*p][1] = r[1];
                    Bh[2*p+1][0] = r[2]; Bh[2*p+1][1] = r[3];
                    ldsm4(r, bl + bo);
                    Bl[2*p][0] = r[0]; Bl[2*p][1] = r[1];
                    Bl[2*p+1][0] = r[2]; Bl[2*p+1][1] = r[3];
                }
            }
#pragma unroll
            for (int mi = 0; mi < 4; mi++)
#pragma unroll
                for (int ni = 0; ni < 4; ni++) {
                    mma_bf16(acc[mi][ni], Ah[mi], Bh[ni]);
                    mma_bf16(acc[mi][ni], Ah[mi], Bl[ni]);
                    mma_bf16(acc[mi][ni], Al[mi], Bh[ni]);
                }
        }
        __syncthreads();
    }
}

// ======================= 2-term fp16 GEMM: C = (Ahi+Alo) * Bhi, B in [k][n] =======================
__device__ __forceinline__ void gemm2_f16(
    const __half* __restrict__ ahi, const __half* __restrict__ alo, int lda,
    const __half* __restrict__ bhi, int ldb,
    int nchunks, float (&acc)[4][4][4])
{
    extern __shared__ char smem[];
    const uint32_t sb = smem_u32(smem);
    const int tid = threadIdx.x;
    const int lane = tid & 31, warp = tid >> 5;
    const int wm = warp >> 2, wn = warp & 3;

#pragma unroll
    for (int mi = 0; mi < 4; mi++)
#pragma unroll
        for (int ni = 0; ni < 4; ni++)
#pragma unroll
            for (int k = 0; k < 4; k++) acc[mi][ni][k] = 0.f;

    auto load_chunk = [&](int buf, int c) {
        const uint32_t ah = sb + (buf * 2 + 0) * A_TILE_B;
        const uint32_t al = sb + (buf * 2 + 1) * A_TILE_B;
        const uint32_t bh = sb + SMEM_B_OFF + buf * 8704;
        int i = tid;
#pragma unroll
        for (int j = 0; j < 2; j++, i += 256) {
            {
                int row = i >> 2, cc = i & 3;
                size_t go = (size_t)row * lda + c * 32 + cc * 8;
                uint32_t so = (uint32_t)row * 80u + (uint32_t)cc * 16u;
                cp16(ah + so, ahi + go);
                cp16(al + so, alo + go);
            }
            {
                int row = i >> 4, cc = i & 15;
                size_t go = (size_t)(c * 32 + row) * ldb + cc * 8;
                uint32_t so = (uint32_t)row * 272u + (uint32_t)cc * 16u;
                cp16(bh + so, bhi + go);
            }
        }
        cp_commit();
    };

    load_chunk(0, 0);
    for (int c = 0; c < nchunks; ++c) {
        const int buf = c & 1;
        if (c + 1 < nchunks) { load_chunk(1 - buf, c + 1); cp_wait<1>(); }
        else                 { cp_wait<0>(); }
        __syncthreads();

        const uint32_t ah = sb + (buf * 2 + 0) * A_TILE_B;
        const uint32_t al = sb + (buf * 2 + 1) * A_TILE_B;
        const uint32_t bh = sb + SMEM_B_OFF + buf * 8704;

#pragma unroll
        for (int ks = 0; ks < 2; ++ks) {
            uint32_t Ah[4][4], Al[4][4], Bh[4][2];
            const uint32_t ao = (uint32_t)(wm * 64 + (lane & 15)) * 80u
                              + (uint32_t)(ks * 16 + (lane >> 4) * 8) * 2u;
#pragma unroll
            for (int mi = 0; mi < 4; mi++) {
                ldsm4(Ah[mi], ah + ao + (uint32_t)(mi * 16) * 80u);
                ldsm4(Al[mi], al + ao + (uint32_t)(mi * 16) * 80u);
            }
            const uint32_t brow = (uint32_t)(ks * 16 + (lane & 15));
#pragma unroll
            for (int p = 0; p < 2; p++) {
                const uint32_t bo = brow * 272u
                    + (uint32_t)(wn * 32 + p * 16 + (lane >> 4) * 8) * 2u;
                uint32_t r[4];
                ldsm4t(r, bh + bo);
                Bh[2*p][0] = r[0]; Bh[2*p][1] = r[1];
                Bh[2*p+1][0] = r[2]; Bh[2*p+1][1] = r[3];
            }
#pragma unroll
            for (int mi = 0; mi < 4; mi++)
#pragma unroll
                for (int ni = 0; ni < 4; ni++) {
                    mma_f16(acc[mi][ni], Ah[mi], Bh[ni]);
                    mma_f16(acc[mi][ni], Al[mi], Bh[ni]);
                }
        }
        __syncthreads();
    }
}

// ======================= kernel: split fp32 -> bf16 hi/lo (x, Wq, Wk, Wv) =======================
__global__ __launch_bounds__(256) void split_kernel(const float* __restrict__ src, int which) {
    __nv_bfloat16 *hi, *lo;
    if (which == 0)      { hi = g_xhi;    lo = g_xlo;    }
    else if (which == 1) { hi = g_whi[0]; lo = g_wlo[0]; }
    else if (which == 2) { hi = g_whi[1]; lo = g_wlo[1]; }
    else                 { hi = g_whi[2]; lo = g_wlo[2]; }
    size_t base = ((size_t)blockIdx.x * 256 + threadIdx.x) * 4;
    float4 v = *reinterpret_cast<const float4*>(src + base);
    float f[4] = {v.x, v.y, v.z, v.w};
    uint32_t hp[2], lp[2];
#pragma unroll
    for (int j = 0; j < 2; j++) {
        __nv_bfloat16 h0 = __float2bfloat16(f[2*j]),   h1 = __float2bfloat16(f[2*j+1]);
        __nv_bfloat16 l0 = __float2bfloat16(f[2*j]   - __bfloat162float(h0));
        __nv_bfloat16 l1 = __float2bfloat16(f[2*j+1] - __bfloat162float(h1));
        hp[j] = (uint32_t)__bfloat16_as_ushort(h0) | ((uint32_t)__bfloat16_as_ushort(h1) << 16);
        lp[j] = (uint32_t)__bfloat16_as_ushort(l0) | ((uint32_t)__bfloat16_as_ushort(l1) << 16);
    }
    *reinterpret_cast<uint2*>(hi + base) = make_uint2(hp[0], hp[1]);
    *reinterpret_cast<uint2*>(lo + base) = make_uint2(lp[0], lp[1]);
}

// ======================= kernel: QKV projection =======================
__global__ __launch_bounds__(256) void qkv_gemm() {
    const int z = blockIdx.z, m0 = blockIdx.y * 128, n0 = blockIdx.x * 128;
    float acc[4][4][4];
    gemm3_bf16<true>(g_xhi + (size_t)m0 * DIM, g_xlo + (size_t)m0 * DIM, DIM,
                     g_whi[z] + n0, g_wlo[z] + n0, DIM, DIM / 32, acc);
    const int lane = threadIdx.x & 31, warp = threadIdx.x >> 5;
    const int g = lane >> 2, t = lane & 3, wm = warp >> 2, wn = warp & 3;
#pragma unroll
    for (int mi = 0; mi < 4; mi++) {
        const int r0 = m0 + wm * 64 + mi * 16 + g;
#pragma unroll
        for (int ni = 0; ni < 4; ni++) {
            const int cc = n0 + wn * 32 + ni * 8 + 2 * t;
            if (z == 2) {
                // V: fp16 hi only
                __half h0 = __float2half_rn(acc[mi][ni][0]);
                __half h1 = __float2half_rn(acc[mi][ni][1]);
                __half h2 = __float2half_rn(acc[mi][ni][2]);
                __half h3 = __float2half_rn(acc[mi][ni][3]);
                *reinterpret_cast<uint32_t*>(g_vh + (size_t)r0 * DIM + cc) =
                    (uint32_t)__half_as_ushort(h0) | ((uint32_t)__half_as_ushort(h1) << 16);
                *reinterpret_cast<uint32_t*>(g_vh + (size_t)(r0 + 8) * DIM + cc) =
                    (uint32_t)__half_as_ushort(h2) | ((uint32_t)__half_as_ushort(h3) << 16);
            } else {
                __nv_bfloat16* oh = (z == 0) ? g_qhi : g_khi;
                __nv_bfloat16* ol = (z == 0) ? g_qlo : g_klo;
                st_split2_bf16(oh, ol, (size_t)r0 * DIM + cc,       acc[mi][ni][0], acc[mi][ni][1]);
                st_split2_bf16(oh, ol, (size_t)(r0 + 8) * DIM + cc, acc[mi][ni][2], acc[mi][ni][3]);
            }
        }
    }
}

// ======================= kernel: fused scores = exp(QK^T * scale) (causal) + rowsum partials =======================
__global__ __launch_bounds__(256) void scores_gemm() {
    if (blockIdx.x > blockIdx.y) return;     // fully-masked tile
    extern __shared__ char smem[];
    const int b = blockIdx.z, q0 = blockIdx.y * 128, k0 = blockIdx.x * 128;
    const size_t boff = (size_t)b * SEQ * DIM;
    float acc[4][4][4];
    gemm3_bf16<false>(g_qhi + boff + (size_t)q0 * DIM, g_qlo + boff + (size_t)q0 * DIM, DIM,
                      g_khi + boff + (size_t)k0 * DIM, g_klo + boff + (size_t)k0 * DIM, DIM,
                      DIM / 32, acc);
    const bool diag = (blockIdx.x == blockIdx.y);
    __half* ph = g_phi + (size_t)b * SEQ * SEQ;
    __half* pl = g_plo + (size_t)b * SEQ * SEQ;
    const int lane = threadIdx.x & 31, warp = threadIdx.x >> 5;
    const int g = lane >> 2, t = lane & 3, wm = warp >> 2, wn = warp & 3;
    const float scale = 0.03125f;

    float* red = reinterpret_cast<float*>(smem);   // [4][128] per-warp-col row partials
    float rs0[4], rs1[4];
#pragma unroll
    for (int mi = 0; mi < 4; mi++) { rs0[mi] = 0.f; rs1[mi] = 0.f; }

#pragma unroll
    for (int mi = 0; mi < 4; mi++) {
        const int r0 = q0 + wm * 64 + mi * 16 + g;
#pragma unroll
        for (int ni = 0; ni < 4; ni++) {
            const int cc = k0 + wn * 32 + ni * 8 + 2 * t;
            float e0 = __expf(acc[mi][ni][0] * scale);
            float e1 = __expf(acc[mi][ni][1] * scale);
            float e2 = __expf(acc[mi][ni][2] * scale);
            float e3 = __expf(acc[mi][ni][3] * scale);
            if (diag) {
                if (cc     > r0)     e0 = 0.f;
                if (cc + 1 > r0)     e1 = 0.f;
                if (cc     > r0 + 8) e2 = 0.f;
                if (cc + 1 > r0 + 8) e3 = 0.f;
            }
            st_split2_f16(ph, pl, (size_t)r0 * SEQ + cc,       e0, e1);
            st_split2_f16(ph, pl, (size_t)(r0 + 8) * SEQ + cc, e2, e3);
            rs0[mi] += e0 + e1;
            rs1[mi] += e2 + e3;
        }
    }
    // reduce row partials: across lane&3 (shfl), then across wn warps via smem
#pragma unroll
    for (int mi = 0; mi < 4; mi++) {
        float s0 = rs0[mi], s1 = rs1[mi];
        s0 += __shfl_xor_sync(0xFFFFFFFFu, s0, 1);
        s0 += __shfl_xor_sync(0xFFFFFFFFu, s0, 2);
        s1 += __shfl_xor_sync(0xFFFFFFFFu, s1, 1);
        s1 += __shfl_xor_sync(0xFFFFFFFFu, s1, 2);
        if (t == 0) {
            const int lr = wm * 64 + mi * 16 + g;
            red[wn * 128 + lr]     = s0;
            red[wn * 128 + lr + 8] = s1;
        }
    }
    __syncthreads();
    if (threadIdx.x < 128) {
        float tot = red[threadIdx.x] + red[128 + threadIdx.x]
                  + red[256 + threadIdx.x] + red[384 + threadIdx.x];
        g_partial[b][blockIdx.x][q0 + threadIdx.x] = tot;
    }
}

// ======================= kernel: rowsum reduce -> 1/sum =======================
__global__ __launch_bounds__(256) void rowsum_kernel() {
    const int idx = blockIdx.x * 256 + threadIdx.x;  // 0..8191
    const int b = idx >> 11, q = idx & (SEQ - 1);
    const int nt = (q >> 7) + 1;
    float s = 0.f;
    for (int j = 0; j < nt; j++) s += g_partial[b][j][q];
    g_rsuminv[idx] = 1.f / s;
}

// ======================= kernel: O = (P @ V) * rsuminv (causal-truncated K) =======================
__global__ __launch_bounds__(256) void pv_gemm(float* __restrict__ outp) {
    const int b = blockIdx.z, q0 = blockIdx.y * 128, n0 = blockIdx.x * 128;
    float acc[4][4][4];
    gemm2_f16(g_phi + (size_t)b * SEQ * SEQ + (size_t)q0 * SEQ,
              g_plo + (size_t)b * SEQ * SEQ + (size_t)q0 * SEQ, SEQ,
              g_vh + (size_t)b * SEQ * DIM + n0, DIM,
              (q0 + 128) / 32, acc);
    float* out = outp + (size_t)b * SEQ * DIM;
    const float* rsi = g_rsuminv + b * SEQ;
    const int lane = threadIdx.x & 31, warp = threadIdx.x >> 5;
    const int g = lane >> 2, t = lane & 3, wm = warp >> 2, wn = warp & 3;
#pragma unroll
    for (int mi = 0; mi < 4; mi++) {
        const int r0 = q0 + wm * 64 + mi * 16 + g;
        const float i0 = rsi[r0], i1 = rsi[r0 + 8];
#pragma unroll
        for (int ni = 0; ni < 4; ni++) {
            const int cc = n0 + wn * 32 + ni * 8 + 2 * t;
            *reinterpret_cast<float2*>(out + (size_t)r0 * DIM + cc) =
                make_float2(acc[mi][ni][0] * i0, acc[mi][ni][1] * i0);
            *reinterpret_cast<float2*>(out + (size_t)(r0 + 8) * DIM + cc) =
                make_float2(acc[mi][ni][2] * i1, acc[mi][ni][3] * i1);
        }
    }
}

// ======================= launch =======================
extern "C" void kernel_launch(void* const* d_in, const int* in_sizes, int n_in,
                              void* d_out, int out_size) {
    const float* x  = (const float*)d_in[0];
    const float* Wq = (const float*)d_in[1];
    const float* Wk = (const float*)d_in[2];
    const float* Wv = (const float*)d_in[3];
    float* out = (float*)d_out;

    cudaFuncSetAttribute(qkv_gemm,    cudaFuncAttributeMaxDynamicSharedMemorySize, SMEM_BYTES);
    cudaFuncSetAttribute(scores_gemm, cudaFuncAttributeMaxDynamicSharedMemorySize, SMEM_BYTES);
    cudaFuncSetAttribute(pv_gemm,     cudaFuncAttributeMaxDynamicSharedMemorySize, SMEM_BYTES);

    split_kernel<<<(size_t)MTOT * DIM / 1024, 256>>>(x, 0);
    split_kernel<<<(size_t)DIM * DIM / 1024, 256>>>(Wq, 1);
    split_kernel<<<(size_t)DIM * DIM / 1024, 256>>>(Wk, 2);
    split_kernel<<<(size_t)DIM * DIM / 1024, 256>>>(Wv, 3);

    qkv_gemm<<<dim3(DIM / 128, MTOT / 128, 3), 256, SMEM_BYTES>>>();
    scores_gemm<<<dim3(SEQ / 128, SEQ / 128, BATCH), 256, SMEM_BYTES>>>();
    rowsum_kernel<<<MTOT / 256, 256>>>();
    pv_gemm<<<dim3(DIM / 128, SEQ / 128, BATCH), 256, SMEM_BYTES>>>(out);
}